// round 5
// baseline (speedup 1.0000x reference)
#include <cuda_runtime.h>
#include <cstdint>
#include <math.h>

// BaseSmear: project 64^3 grid points into 8 camera images, nearest-neighbor
// gather of 32 feature channels + depth + validity + ray direction.
//
//   1) transpose images [I,C,H,W] -> [I,H,W,C] (channels-last) into scratch.
//   2) smear: 1 point/thread compute (low regs, high occ), results staged in
//      smem, block-cooperative float4 output stores (store wavefronts / 4).

#define II 8
#define CC 32
#define HH 240
#define WW 320
#define HW (HH*WW)          // 76800
#define NN (64*64*64)       // 262144
#define NN4 (NN/4)          // 65536

__device__ float g_imgT[(size_t)II * HW * CC];   // 78.6 MB channels-last scratch

// ---- Phase 1: [C, HW] -> [HW, C] tile transpose per image ------------------
__global__ __launch_bounds__(256) void transpose_kernel(const float* __restrict__ images) {
    __shared__ float tile[32][33];
    const int tilesPerImg = HW / 32;                 // 2400
    const int i       = blockIdx.x / tilesPerImg;
    const int pixbase = (blockIdx.x % tilesPerImg) * 32;
    const int lane = threadIdx.x & 31;
    const int wy   = threadIdx.x >> 5;               // 0..7

    const float* src = images + (size_t)i * CC * HW + pixbase;
    #pragma unroll
    for (int r = 0; r < 4; r++) {
        const int c = wy + r * 8;
        tile[c][lane] = src[(size_t)c * HW + lane];  // coalesced 128B read per warp
    }
    __syncthreads();
    float* dst = g_imgT + ((size_t)i * HW + pixbase) * CC;
    #pragma unroll
    for (int r = 0; r < 4; r++) {
        const int p = wy + r * 8;
        dst[(size_t)p * CC + lane] = tile[lane][p];  // coalesced 128B write per warp
    }
}

// ---- Phase 2: project + gather -> smem stage -> float4 stores --------------
__global__ __launch_bounds__(256) void smear_kernel(
    const float* __restrict__ trans,    // [8,3,4]
    const float* __restrict__ Tcw,      // [8,4,4]
    const float* __restrict__ coords,   // [3,64,64,64]
    float* __restrict__ out)            // [8,37,N] then [3,N]
{
    __shared__ float s[37][256];        // 37,888 B -> 6 blocks/SM

    const int tid = threadIdx.x;
    const int bid = blockIdx.x;
    const int i   = bid >> 10;               // 1024 blocks per image
    const int nb  = (bid & 1023) << 8;       // block's base point
    const int n   = nb + tid;

    const float px = coords[n];
    const float py = coords[NN + n];
    const float pz = coords[2 * NN + n];

    const float* T = Tcw   + i * 16;   // rows of 4x4 world->cam
    const float* P = trans + i * 12;   // rows of 3x4 projection

    const float depth = T[8] * px + T[9] * py + T[10] * pz + T[11];

    const float w  = P[8] * px + P[9] * py + P[10] * pz + P[11];
    const float ws = (fabsf(w) < 1e-8f) ? 1e-8f : w;
    const float u  = (P[0] * px + P[1] * py + P[2] * pz + P[3]) / ws;
    const float v  = (P[4] * px + P[5] * py + P[6] * pz + P[7]) / ws;

    const bool valid = (u >= 0.0f) && (u <= (float)(WW - 1)) &&
                       (v >= 0.0f) && (v <= (float)(HH - 1)) &&
                       (depth > 0.0f);
    const float validf = valid ? 1.0f : 0.0f;

    // jnp.round == round-half-to-even == rintf (default rounding mode)
    const int ui = (int)fminf(fmaxf(rintf(u), 0.0f), (float)(WW - 1));
    const int vi = (int)fminf(fmaxf(rintf(v), 0.0f), (float)(HH - 1));
    const int poff = vi * WW + ui;

    // camera center = -R^T t
    const float ccx = -(T[0] * T[3] + T[4] * T[7] + T[8]  * T[11]);
    const float ccy = -(T[1] * T[3] + T[5] * T[7] + T[9]  * T[11]);
    const float ccz = -(T[2] * T[3] + T[6] * T[7] + T[10] * T[11]);
    float dx = px - ccx, dy = py - ccy, dz = pz - ccz;
    const float inv = 1.0f / (sqrtf(dx * dx + dy * dy + dz * dz) + 1e-8f);

    // gather 8x float4 (128B aligned, L2-resident), stage into smem
    const float4* img4 = (const float4*)(g_imgT + ((size_t)i * HW + poff) * CC);
    const float4 z4 = make_float4(0.f, 0.f, 0.f, 0.f);
    #pragma unroll
    for (int k = 0; k < 8; k++) {
        const float4 f = valid ? __ldg(img4 + k) : z4;
        s[4 * k + 0][tid] = f.x;
        s[4 * k + 1][tid] = f.y;
        s[4 * k + 2][tid] = f.z;
        s[4 * k + 3][tid] = f.w;
    }
    s[32][tid] = depth;
    s[33][tid] = validf;
    s[34][tid] = dx * inv;
    s[35][tid] = dy * inv;
    s[36][tid] = dz * inv;

    // coordinates passthrough: image-0 blocks write the tail (coalesced scalar)
    if (i == 0) {
        float* tail = out + (size_t)II * 37 * NN;
        tail[n]          = px;
        tail[NN + n]     = py;
        tail[2 * NN + n] = pz;
    }

    __syncthreads();

    // block-cooperative output: 37 channels x 64 float4, fully coalesced STG.128
    float4* o4 = (float4*)out + (size_t)i * 37 * NN4 + (nb >> 2);
    #pragma unroll
    for (int idx = tid; idx < 37 * 64; idx += 256) {
        const int ch = idx >> 6;
        const int q  = idx & 63;
        o4[(size_t)ch * NN4 + q] = ((const float4*)s[ch])[q];
    }
}

extern "C" void kernel_launch(void* const* d_in, const int* in_sizes, int n_in,
                              void* d_out, int out_size) {
    const float* images = (const float*)d_in[0];
    const float* trans  = (const float*)d_in[1];
    const float* Tcw    = (const float*)d_in[2];
    const float* coords = (const float*)d_in[3];
    float* out = (float*)d_out;

    transpose_kernel<<<II * (HW / 32), 256>>>(images);
    smear_kernel<<<II * (NN / 256), 256>>>(trans, Tcw, coords, out);
}

// round 6
// speedup vs baseline: 1.1626x; 1.1626x over previous
#include <cuda_runtime.h>
#include <cstdint>
#include <math.h>

// BaseSmear: project 64^3 grid points into 8 camera images, nearest-neighbor
// gather of 32 feature channels + depth + validity + ray direction.
//
//   1) transpose images [I,C,H,W] -> [I,H,W,C] (channels-last) scratch.
//   2) smear: per-thread projection; COOPERATIVE gather (8 lanes share one
//      pixel's 128B channel vector -> 1 L1 wavefront per point instead of 8),
//      XOR-swizzled smem staging (conflict-free both sides), STG.128 out.

#define II 8
#define CC 32
#define HH 240
#define WW 320
#define HW (HH*WW)          // 76800
#define NN (64*64*64)       // 262144
#define NN4 (NN/4)          // 65536

__device__ float g_imgT[(size_t)II * HW * CC];   // 78.6 MB channels-last scratch

// ---- Phase 1: [C, HW] -> [HW, C] tile transpose per image ------------------
__global__ __launch_bounds__(256) void transpose_kernel(const float* __restrict__ images) {
    __shared__ float tile[32][33];
    const int tilesPerImg = HW / 32;                 // 2400
    const int i       = blockIdx.x / tilesPerImg;
    const int pixbase = (blockIdx.x % tilesPerImg) * 32;
    const int lane = threadIdx.x & 31;
    const int wy   = threadIdx.x >> 5;               // 0..7

    const float* src = images + (size_t)i * CC * HW + pixbase;
    #pragma unroll
    for (int r = 0; r < 4; r++) {
        const int c = wy + r * 8;
        tile[c][lane] = src[(size_t)c * HW + lane];
    }
    __syncthreads();
    float* dst = g_imgT + ((size_t)i * HW + pixbase) * CC;
    #pragma unroll
    for (int r = 0; r < 4; r++) {
        const int p = wy + r * 8;
        dst[(size_t)p * CC + lane] = tile[lane][p];
    }
}

// swizzled smem index: channel-major rows of 256, pixel index XORed by (ch&28)
__device__ __forceinline__ int sidx(int ch, int pt) {
    return ch * 256 + (pt ^ (ch & 28));
}

// ---- Phase 2: project + cooperative gather + swizzled stage + STG.128 ------
__global__ __launch_bounds__(256) void smear_kernel(
    const float* __restrict__ trans,    // [8,3,4]
    const float* __restrict__ Tcw,      // [8,4,4]
    const float* __restrict__ coords,   // [3,64,64,64]
    float* __restrict__ out)            // [8,37,N] then [3,N]
{
    __shared__ float s[37 * 256];       // 37,888 B, swizzled channel-major
    __shared__ int   spoff[256];        // encoded pixel offset (<0 => invalid)

    const int tid = threadIdx.x;
    const int bid = blockIdx.x;
    const int i   = bid >> 10;               // 1024 blocks per image
    const int nb  = (bid & 1023) << 8;       // block's base point
    const int n   = nb + tid;

    // ---------- Phase A: per-thread projection ----------
    const float px = coords[n];
    const float py = coords[NN + n];
    const float pz = coords[2 * NN + n];

    const float* T = Tcw   + i * 16;
    const float* P = trans + i * 12;

    const float depth = T[8] * px + T[9] * py + T[10] * pz + T[11];
    const float w  = P[8] * px + P[9] * py + P[10] * pz + P[11];
    const float ws = (fabsf(w) < 1e-8f) ? 1e-8f : w;
    const float u  = (P[0] * px + P[1] * py + P[2] * pz + P[3]) / ws;
    const float v  = (P[4] * px + P[5] * py + P[6] * pz + P[7]) / ws;

    const bool valid = (u >= 0.0f) && (u <= (float)(WW - 1)) &&
                       (v >= 0.0f) && (v <= (float)(HH - 1)) &&
                       (depth > 0.0f);
    const float validf = valid ? 1.0f : 0.0f;

    const int ui = (int)fminf(fmaxf(rintf(u), 0.0f), (float)(WW - 1));
    const int vi = (int)fminf(fmaxf(rintf(v), 0.0f), (float)(HH - 1));
    spoff[tid] = valid ? (vi * WW + ui) : -1;

    const float ccx = -(T[0] * T[3] + T[4] * T[7] + T[8]  * T[11]);
    const float ccy = -(T[1] * T[3] + T[5] * T[7] + T[9]  * T[11]);
    const float ccz = -(T[2] * T[3] + T[6] * T[7] + T[10] * T[11]);
    float dx = px - ccx, dy = py - ccy, dz = pz - ccz;
    const float inv = 1.0f / (sqrtf(dx * dx + dy * dy + dz * dz) + 1e-8f);

    s[sidx(32, tid)] = depth;
    s[sidx(33, tid)] = validf;
    s[sidx(34, tid)] = dx * inv;
    s[sidx(35, tid)] = dy * inv;
    s[sidx(36, tid)] = dz * inv;

    // coordinates passthrough: image-0 blocks write the tail (coalesced)
    if (i == 0) {
        float* tail = out + (size_t)II * 37 * NN;
        tail[n]          = px;
        tail[NN + n]     = py;
        tail[2 * NN + n] = pz;
    }

    __syncthreads();

    // ---------- Phase B: cooperative gather (8 lanes per pixel) ----------
    const int lane  = tid & 31;
    const int wbase = tid & ~31;             // warp's first point (local)
    const int chunk = lane & 7;              // which 16B of the 128B pixel vec
    const int ptoff = lane >> 3;             // which of 4 pixels this instr

    const float* imgBase = g_imgT + (size_t)i * HW * CC + chunk * 4;

    #pragma unroll
    for (int it = 0; it < 8; it++) {
        const int q  = wbase + it * 4 + ptoff;   // local point index
        const int pe = spoff[q];                 // broadcast within 8 lanes
        float4 f = make_float4(0.f, 0.f, 0.f, 0.f);
        if (pe >= 0)
            f = __ldg((const float4*)(imgBase + (size_t)pe * CC));
        const int ch = chunk * 4;
        s[sidx(ch + 0, q)] = f.x;
        s[sidx(ch + 1, q)] = f.y;
        s[sidx(ch + 2, q)] = f.z;
        s[sidx(ch + 3, q)] = f.w;
    }

    __syncthreads();

    // ---------- Phase C: coalesced float4 output ----------
    float4* o4 = (float4*)out + (size_t)i * 37 * NN4 + (nb >> 2);
    #pragma unroll
    for (int idx = tid; idx < 37 * 64; idx += 256) {
        const int ch = idx >> 6;
        const int q4 = idx & 63;
        // sw = ch&28 is a multiple of 4, so the float4 group stays contiguous
        const float4 val = *(const float4*)&s[ch * 256 + ((q4 * 4) ^ (ch & 28))];
        o4[(size_t)ch * NN4 + q4] = val;
    }
}

extern "C" void kernel_launch(void* const* d_in, const int* in_sizes, int n_in,
                              void* d_out, int out_size) {
    const float* images = (const float*)d_in[0];
    const float* trans  = (const float*)d_in[1];
    const float* Tcw    = (const float*)d_in[2];
    const float* coords = (const float*)d_in[3];
    float* out = (float*)d_out;

    transpose_kernel<<<II * (HW / 32), 256>>>(images);
    smear_kernel<<<II * (NN / 256), 256>>>(trans, Tcw, coords, out);
}

// round 7
// speedup vs baseline: 1.3236x; 1.1385x over previous
#include <cuda_runtime.h>
#include <cstdint>
#include <math.h>

// BaseSmear: project 64^3 grid points into 8 camera images, nearest-neighbor
// gather of 32 feature channels + depth + validity + ray direction.
//
//   1) transpose images [I,C,H,W] -> [I,H,W,C] (channels-last) scratch.
//   2) smear: per-thread projection; cooperative gather (8 lanes share one
//      pixel's 128B channel vector), pixel offsets exchanged via SHFL (no
//      smem pointer-chase, no sync before gather), 32KB swizzled smem stage
//      for features only, extras stored direct, STG.128 + __stcs out.

#define II 8
#define CC 32
#define HH 240
#define WW 320
#define HW (HH*WW)          // 76800
#define NN (64*64*64)       // 262144
#define NN4 (NN/4)          // 65536

__device__ float g_imgT[(size_t)II * HW * CC];   // 78.6 MB channels-last scratch

// ---- Phase 1: [C, HW] -> [HW, C] tile transpose per image ------------------
__global__ __launch_bounds__(256) void transpose_kernel(const float* __restrict__ images) {
    __shared__ float tile[32][33];
    const int tilesPerImg = HW / 32;                 // 2400
    const int i       = blockIdx.x / tilesPerImg;
    const int pixbase = (blockIdx.x % tilesPerImg) * 32;
    const int lane = threadIdx.x & 31;
    const int wy   = threadIdx.x >> 5;               // 0..7

    const float* src = images + (size_t)i * CC * HW + pixbase;
    #pragma unroll
    for (int r = 0; r < 4; r++) {
        const int c = wy + r * 8;
        tile[c][lane] = src[(size_t)c * HW + lane];
    }
    __syncthreads();
    float* dst = g_imgT + ((size_t)i * HW + pixbase) * CC;
    #pragma unroll
    for (int r = 0; r < 4; r++) {
        const int p = wy + r * 8;
        dst[(size_t)p * CC + lane] = tile[lane][p];
    }
}

// swizzled smem index: channel-major rows of 256, point index XORed by (ch&28)
__device__ __forceinline__ int sidx(int ch, int pt) {
    return ch * 256 + (pt ^ (ch & 28));
}

// ---- Phase 2: project + SHFL-coop gather + swizzled stage + STG.128 --------
__global__ __launch_bounds__(256) void smear_kernel(
    const float* __restrict__ trans,    // [8,3,4]
    const float* __restrict__ Tcw,      // [8,4,4]
    const float* __restrict__ coords,   // [3,64,64,64]
    float* __restrict__ out)            // [8,37,N] then [3,N]
{
    __shared__ float s[32 * 256];       // 32 KB -> 7 blocks/SM

    const int tid = threadIdx.x;
    const int bid = blockIdx.x;
    const int i   = bid >> 10;               // 1024 blocks per image
    const int nb  = (bid & 1023) << 8;       // block's base point
    const int n   = nb + tid;

    // ---------- Phase A: per-thread projection ----------
    const float px = coords[n];
    const float py = coords[NN + n];
    const float pz = coords[2 * NN + n];

    const float* T = Tcw   + i * 16;
    const float* P = trans + i * 12;

    const float depth = T[8] * px + T[9] * py + T[10] * pz + T[11];
    const float w  = P[8] * px + P[9] * py + P[10] * pz + P[11];
    const float ws = (fabsf(w) < 1e-8f) ? 1e-8f : w;
    const float u  = (P[0] * px + P[1] * py + P[2] * pz + P[3]) / ws;
    const float v  = (P[4] * px + P[5] * py + P[6] * pz + P[7]) / ws;

    const bool valid = (u >= 0.0f) && (u <= (float)(WW - 1)) &&
                       (v >= 0.0f) && (v <= (float)(HH - 1)) &&
                       (depth > 0.0f);
    const float validf = valid ? 1.0f : 0.0f;

    const int ui = (int)fminf(fmaxf(rintf(u), 0.0f), (float)(WW - 1));
    const int vi = (int)fminf(fmaxf(rintf(v), 0.0f), (float)(HH - 1));
    const int poffEnc = valid ? (vi * WW + ui) : -1;

    const float ccx = -(T[0] * T[3] + T[4] * T[7] + T[8]  * T[11]);
    const float ccy = -(T[1] * T[3] + T[5] * T[7] + T[9]  * T[11]);
    const float ccz = -(T[2] * T[3] + T[6] * T[7] + T[10] * T[11]);
    float dx = px - ccx, dy = py - ccy, dz = pz - ccz;
    const float inv = 1.0f / (sqrtf(dx * dx + dy * dy + dz * dz) + 1e-8f);

    // extras + coords passthrough: direct streamed stores (coalesced scalar)
    {
        float* eo = out + (size_t)i * 37 * NN + n;
        __stcs(eo + (size_t)32 * NN, depth);
        __stcs(eo + (size_t)33 * NN, validf);
        __stcs(eo + (size_t)34 * NN, dx * inv);
        __stcs(eo + (size_t)35 * NN, dy * inv);
        __stcs(eo + (size_t)36 * NN, dz * inv);
        if (i == 0) {
            float* tail = out + (size_t)II * 37 * NN;
            __stcs(tail + n,          px);
            __stcs(tail + NN + n,     py);
            __stcs(tail + 2 * NN + n, pz);
        }
    }

    // ---------- Phase B: cooperative gather (8 lanes per pixel), SHFL poff ---
    const int lane  = tid & 31;
    const int wbase = tid & ~31;             // warp's first point (local)
    const int chunk = lane & 7;              // which 16B of the 128B pixel vec
    const int ptoff = lane >> 3;             // which of 4 pixels this instr

    const float* imgBase = g_imgT + (size_t)i * HW * CC + chunk * 4;
    const float4 z4 = make_float4(0.f, 0.f, 0.f, 0.f);
    const int ch = chunk * 4;

    #pragma unroll
    for (int it = 0; it < 8; it++) {
        const int pe = __shfl_sync(0xffffffffu, poffEnc, it * 4 + ptoff);
        float4 f = z4;
        if (pe >= 0)
            f = __ldg((const float4*)(imgBase + (size_t)pe * CC));
        const int q = wbase + it * 4 + ptoff;
        s[sidx(ch + 0, q)] = f.x;
        s[sidx(ch + 1, q)] = f.y;
        s[sidx(ch + 2, q)] = f.z;
        s[sidx(ch + 3, q)] = f.w;
    }

    __syncthreads();

    // ---------- Phase C: coalesced float4 streamed output ----------
    float4* o4 = (float4*)out + (size_t)i * 37 * NN4 + (nb >> 2);
    #pragma unroll
    for (int r = 0; r < 8; r++) {
        const int idx = r * 256 + tid;
        const int c  = idx >> 6;            // 0..31
        const int q4 = idx & 63;
        // swizzle offset is a multiple of 4 -> float4 group stays contiguous
        const float4 val = *(const float4*)&s[c * 256 + ((q4 * 4) ^ (c & 28))];
        __stcs(&o4[(size_t)c * NN4 + q4], val);
    }
}

extern "C" void kernel_launch(void* const* d_in, const int* in_sizes, int n_in,
                              void* d_out, int out_size) {
    const float* images = (const float*)d_in[0];
    const float* trans  = (const float*)d_in[1];
    const float* Tcw    = (const float*)d_in[2];
    const float* coords = (const float*)d_in[3];
    float* out = (float*)d_out;

    transpose_kernel<<<II * (HW / 32), 256>>>(images);
    smear_kernel<<<II * (NN / 256), 256>>>(trans, Tcw, coords, out);
}

// round 8
// speedup vs baseline: 1.3482x; 1.0186x over previous
#include <cuda_runtime.h>
#include <cstdint>
#include <math.h>

// BaseSmear: project 64^3 grid points into 8 camera images, nearest-neighbor
// gather of 32 feature channels + depth + validity + ray direction.
//
//   1) transpose images [I,C,H,W] -> [I,H,W,C] (channels-last) scratch.
//   2) smear: per-thread projection; cooperative gather (8 lanes share one
//      pixel's 128B channel vector, offsets via SHFL); WARP-LOCAL swizzled
//      smem staging (no __syncthreads at all -> warps flow independently),
//      STG.128 + __stcs streaming output.

#define II 8
#define CC 32
#define HH 240
#define WW 320
#define HW (HH*WW)          // 76800
#define NN (64*64*64)       // 262144
#define NN4 (NN/4)          // 65536

__device__ float g_imgT[(size_t)II * HW * CC];   // 78.6 MB channels-last scratch

// ---- Phase 1: [C, HW] -> [HW, C] tile transpose per image ------------------
__global__ __launch_bounds__(256) void transpose_kernel(const float* __restrict__ images) {
    __shared__ float tile[32][33];
    const int tilesPerImg = HW / 32;                 // 2400
    const int i       = blockIdx.x / tilesPerImg;
    const int pixbase = (blockIdx.x % tilesPerImg) * 32;
    const int lane = threadIdx.x & 31;
    const int wy   = threadIdx.x >> 5;               // 0..7

    const float* src = images + (size_t)i * CC * HW + pixbase;
    #pragma unroll
    for (int r = 0; r < 4; r++) {
        const int c = wy + r * 8;
        tile[c][lane] = src[(size_t)c * HW + lane];
    }
    __syncthreads();
    float* dst = g_imgT + ((size_t)i * HW + pixbase) * CC;
    #pragma unroll
    for (int r = 0; r < 4; r++) {
        const int p = wy + r * 8;
        dst[(size_t)p * CC + lane] = tile[lane][p];
    }
}

// ---- Phase 2: project + SHFL-coop gather + warp-local stage + STG.128 ------
__global__ __launch_bounds__(256) void smear_kernel(
    const float* __restrict__ trans,    // [8,3,4]
    const float* __restrict__ Tcw,      // [8,4,4]
    const float* __restrict__ coords,   // [3,64,64,64]
    float* __restrict__ out)            // [8,37,N] then [3,N]
{
    __shared__ float s[8][32 * 32];     // 4 KB per warp, 32 KB total

    const int tid  = threadIdx.x;
    const int lane = tid & 31;
    const int wrp  = tid >> 5;
    const int bid  = blockIdx.x;
    const int i    = bid >> 10;              // 1024 blocks per image
    const int nb   = (bid & 1023) << 8;      // block's base point
    const int n    = nb + tid;

    // ---------- Phase A: per-thread projection ----------
    const float px = coords[n];
    const float py = coords[NN + n];
    const float pz = coords[2 * NN + n];

    const float* T = Tcw   + i * 16;
    const float* P = trans + i * 12;

    const float depth = T[8] * px + T[9] * py + T[10] * pz + T[11];
    const float w  = P[8] * px + P[9] * py + P[10] * pz + P[11];
    const float ws = (fabsf(w) < 1e-8f) ? 1e-8f : w;
    const float u  = (P[0] * px + P[1] * py + P[2] * pz + P[3]) / ws;
    const float v  = (P[4] * px + P[5] * py + P[6] * pz + P[7]) / ws;

    const bool valid = (u >= 0.0f) && (u <= (float)(WW - 1)) &&
                       (v >= 0.0f) && (v <= (float)(HH - 1)) &&
                       (depth > 0.0f);
    const float validf = valid ? 1.0f : 0.0f;

    const int ui = (int)fminf(fmaxf(rintf(u), 0.0f), (float)(WW - 1));
    const int vi = (int)fminf(fmaxf(rintf(v), 0.0f), (float)(HH - 1));
    const int poffEnc = valid ? (vi * WW + ui) : -1;

    const float ccx = -(T[0] * T[3] + T[4] * T[7] + T[8]  * T[11]);
    const float ccy = -(T[1] * T[3] + T[5] * T[7] + T[9]  * T[11]);
    const float ccz = -(T[2] * T[3] + T[6] * T[7] + T[10] * T[11]);
    float dx = px - ccx, dy = py - ccy, dz = pz - ccz;
    const float inv = 1.0f / (sqrtf(dx * dx + dy * dy + dz * dz) + 1e-8f);

    // extras + coords passthrough: direct streamed stores (coalesced scalar)
    {
        float* eo = out + (size_t)i * 37 * NN + n;
        __stcs(eo + (size_t)32 * NN, depth);
        __stcs(eo + (size_t)33 * NN, validf);
        __stcs(eo + (size_t)34 * NN, dx * inv);
        __stcs(eo + (size_t)35 * NN, dy * inv);
        __stcs(eo + (size_t)36 * NN, dz * inv);
        if (i == 0) {
            float* tail = out + (size_t)II * 37 * NN;
            __stcs(tail + n,          px);
            __stcs(tail + NN + n,     py);
            __stcs(tail + 2 * NN + n, pz);
        }
    }

    // ---------- Phase B: cooperative gather (8 lanes per pixel), SHFL poff ---
    const int chunk = lane & 7;              // which 16B of the 128B pixel vec
    const int ptoff = lane >> 3;             // which of 4 points this instr

    const float* imgBase = g_imgT + (size_t)i * HW * CC + chunk * 4;
    const float4 z4 = make_float4(0.f, 0.f, 0.f, 0.f);
    const int ch = chunk * 4;
    float* sw = s[wrp];

    #pragma unroll
    for (int it = 0; it < 8; it++) {
        const int q  = it * 4 + ptoff;       // point index within warp (0..31)
        const int pe = __shfl_sync(0xffffffffu, poffEnc, q);
        float4 f = z4;
        if (pe >= 0)
            f = __ldg((const float4*)(imgBase + (size_t)pe * CC));
        // swizzle: physical pt = q ^ (ch&28); ch&28 = 4*chunk here
        const int base = ch * 32 + (q ^ (chunk * 4));
        sw[base]      = f.x;   // ch+0..3 share (ch&28)=4*chunk
        sw[base + 32] = f.y;
        sw[base + 64] = f.z;
        sw[base + 96] = f.w;
    }

    __syncwarp();

    // ---------- Phase C: warp-local coalesced float4 streamed output ----------
    // warp covers points nb+32*wrp .. +31 -> quad base:
    float4* o4 = (float4*)out + (size_t)i * 37 * NN4 + (nb >> 2) + wrp * 8;
    #pragma unroll
    for (int r = 0; r < 8; r++) {
        const int c  = r * 4 + (lane >> 3);  // channel 0..31
        const int qq = lane & 7;             // float4 index within warp (0..7)
        // (qq*4) ^ (c&28): multiple of 4 -> float4 group stays contiguous
        const float4 val = *(const float4*)&sw[c * 32 + ((qq * 4) ^ (c & 28))];
        __stcs(&o4[(size_t)c * NN4 + qq], val);
    }
}

extern "C" void kernel_launch(void* const* d_in, const int* in_sizes, int n_in,
                              void* d_out, int out_size) {
    const float* images = (const float*)d_in[0];
    const float* trans  = (const float*)d_in[1];
    const float* Tcw    = (const float*)d_in[2];
    const float* coords = (const float*)d_in[3];
    float* out = (float*)d_out;

    transpose_kernel<<<II * (HW / 32), 256>>>(images);
    smear_kernel<<<II * (NN / 256), 256>>>(trans, Tcw, coords, out);
}